// round 5
// baseline (speedup 1.0000x reference)
#include <cuda_runtime.h>

#define TOKENS 4096
#define DIMSZ  1024
#define NSEQ   2048
#define HEADS  16
#define DHEAD  64
#define QKV_N  3072

// Scratch (device globals per harness rules)
__device__ float g_xn [TOKENS * DIMSZ];
__device__ float g_qkv[TOKENS * QKV_N];
__device__ float g_att[TOKENS * DIMSZ];

typedef unsigned long long ull;

// ---- packed fp32x2 helpers (Blackwell FFMA2 path; bit-exact fp32 per lane) ----
__device__ __forceinline__ ull fma2(ull a, ull b, ull c) {
    ull d;
    asm("fma.rn.f32x2 %0, %1, %2, %3;" : "=l"(d) : "l"(a), "l"(b), "l"(c));
    return d;
}
__device__ __forceinline__ ull mul2(ull a, ull b) {
    ull d;
    asm("mul.rn.f32x2 %0, %1, %2;" : "=l"(d) : "l"(a), "l"(b));
    return d;
}
__device__ __forceinline__ ull dup2(float v) {
    ull r;
    asm("mov.b64 %0, {%1, %1};" : "=l"(r) : "f"(v));
    return r;
}
__device__ __forceinline__ float2 unpk(ull v) {
    float2 r;
    asm("mov.b64 {%0, %1}, %2;" : "=f"(r.x), "=f"(r.y) : "l"(v));
    return r;
}

// ---------------------------------------------------------------------------
// RMSNorm
// ---------------------------------------------------------------------------
__global__ void __launch_bounds__(256) rmsnorm_kernel(const float* __restrict__ x,
                                                      const float* __restrict__ gamma) {
    int row = blockIdx.x;
    int tid = threadIdx.x;
    const float4 v = ((const float4*)(x + (size_t)row * DIMSZ))[tid];
    float ss = v.x * v.x + v.y * v.y + v.z * v.z + v.w * v.w;
#pragma unroll
    for (int off = 16; off >= 1; off >>= 1)
        ss += __shfl_xor_sync(0xffffffffu, ss, off);
    __shared__ float red[8];
    int lane = tid & 31, wid = tid >> 5;
    if (lane == 0) red[wid] = ss;
    __syncthreads();
    if (wid == 0) {
        float t = (lane < 8) ? red[lane] : 0.0f;
#pragma unroll
        for (int off = 4; off >= 1; off >>= 1)
            t += __shfl_xor_sync(0xffffffffu, t, off);
        if (lane == 0) red[0] = t;
    }
    __syncthreads();
    float norm = fmaxf(sqrtf(red[0]), 1e-12f);
    float scl = 32.0f / norm;
    const float4 g = ((const float4*)gamma)[tid];
    float4 o;
    o.x = v.x * scl * g.x;
    o.y = v.y * scl * g.y;
    o.z = v.z * scl * g.z;
    o.w = v.w * scl * g.w;
    ((float4*)(g_xn + (size_t)row * DIMSZ))[tid] = o;
}

// ---------------------------------------------------------------------------
// Packed-f32x2 SGEMM: C[M,N] = A[M,1024] @ B[1024,N].
// 128x128 tile, 8x8/thread (accumulators packed 2-wide over N).
// A duplicated in smem ((a,a) pairs) so broadcast operands need no movs.
// Double-buffered: 1 sync per 16-wide K slab, LDG prefetch overlaps compute.
// ---------------------------------------------------------------------------
__global__ void __launch_bounds__(256, 2) sgemm_kernel(const float* __restrict__ A,
                                                       const float* __restrict__ B,
                                                       float* __restrict__ C, int N) {
    __shared__ float Ad[2][16][256];   // 32 KB (duplicated A, transposed)
    __shared__ float Bs[2][16][128];   // 16 KB
    const int K = DIMSZ;
    int tid = threadIdx.x;
    int tx = tid & 15, ty = tid >> 4;
    int bm = blockIdx.y * 128, bn = blockIdx.x * 128;

    // fill buffer 0 (slab 0)
#pragma unroll
    for (int t = 0; t < 2; t++) {
        int idx = tid + t * 256;
        int ra = idx >> 2, ka = (idx & 3) << 2;
        float4 a4 = *(const float4*)&A[(size_t)(bm + ra) * K + ka];
        *(float2*)&Ad[0][ka + 0][2 * ra] = make_float2(a4.x, a4.x);
        *(float2*)&Ad[0][ka + 1][2 * ra] = make_float2(a4.y, a4.y);
        *(float2*)&Ad[0][ka + 2][2 * ra] = make_float2(a4.z, a4.z);
        *(float2*)&Ad[0][ka + 3][2 * ra] = make_float2(a4.w, a4.w);
        int rb = idx >> 5, cb = (idx & 31) << 2;
        *(float4*)&Bs[0][rb][cb] = *(const float4*)&B[(size_t)rb * N + bn + cb];
    }
    __syncthreads();

    ull c2[8][4];
#pragma unroll
    for (int i = 0; i < 8; i++)
#pragma unroll
        for (int j = 0; j < 4; j++) c2[i][j] = 0ull;

    float4 av[2], bv[2];
    const int NSLAB = K / 16;  // 64
    for (int s = 0; s < NSLAB; s++) {
        int cur = s & 1;
        if (s < NSLAB - 1) {
            int k0 = (s + 1) * 16;
#pragma unroll
            for (int t = 0; t < 2; t++) {
                int idx = tid + t * 256;
                int ra = idx >> 2, ka = (idx & 3) << 2;
                av[t] = *(const float4*)&A[(size_t)(bm + ra) * K + k0 + ka];
                int rb = idx >> 5, cb = (idx & 31) << 2;
                bv[t] = *(const float4*)&B[(size_t)(k0 + rb) * N + bn + cb];
            }
        }
#pragma unroll
        for (int k = 0; k < 16; k++) {
            ulonglong2 a01 = *(ulonglong2*)&Ad[cur][k][ty * 8];
            ulonglong2 a23 = *(ulonglong2*)&Ad[cur][k][ty * 8 + 4];
            ulonglong2 a45 = *(ulonglong2*)&Ad[cur][k][128 + ty * 8];
            ulonglong2 a67 = *(ulonglong2*)&Ad[cur][k][128 + ty * 8 + 4];
            ulonglong2 b01 = *(ulonglong2*)&Bs[cur][k][tx * 4];
            ulonglong2 b23 = *(ulonglong2*)&Bs[cur][k][64 + tx * 4];
            ull a[8] = {a01.x, a01.y, a23.x, a23.y, a45.x, a45.y, a67.x, a67.y};
            ull b[4] = {b01.x, b01.y, b23.x, b23.y};
#pragma unroll
            for (int i = 0; i < 8; i++)
#pragma unroll
                for (int j = 0; j < 4; j++)
                    c2[i][j] = fma2(a[i], b[j], c2[i][j]);
        }
        if (s < NSLAB - 1) {
            int nxt = cur ^ 1;
#pragma unroll
            for (int t = 0; t < 2; t++) {
                int idx = tid + t * 256;
                int ra = idx >> 2, ka = (idx & 3) << 2;
                *(float2*)&Ad[nxt][ka + 0][2 * ra] = make_float2(av[t].x, av[t].x);
                *(float2*)&Ad[nxt][ka + 1][2 * ra] = make_float2(av[t].y, av[t].y);
                *(float2*)&Ad[nxt][ka + 2][2 * ra] = make_float2(av[t].z, av[t].z);
                *(float2*)&Ad[nxt][ka + 3][2 * ra] = make_float2(av[t].w, av[t].w);
                int rb = idx >> 5, cb = (idx & 31) << 2;
                *(float4*)&Bs[nxt][rb][cb] = bv[t];
            }
            __syncthreads();
        }
    }

#pragma unroll
    for (int i = 0; i < 8; i++) {
        int row = bm + ((i < 4) ? (ty * 4 + i) : (64 + ty * 4 + (i - 4)));
        float2 p0 = unpk(c2[i][0]), p1 = unpk(c2[i][1]);
        float2 p2 = unpk(c2[i][2]), p3 = unpk(c2[i][3]);
        *(float4*)&C[(size_t)row * N + bn + tx * 4]      = make_float4(p0.x, p0.y, p1.x, p1.y);
        *(float4*)&C[(size_t)row * N + bn + 64 + tx * 4] = make_float4(p2.x, p2.y, p3.x, p3.y);
    }
}

// ---------------------------------------------------------------------------
// Causal flash attention, packed f32x2. Br = Bc = 64, dh = 64, 256 threads.
// Smem (dynamic, 97 KB):
//   Qd[64][128]  Q transposed + duplicated by q-row  (32 KB)
//   Kt[64][68]   K transposed, padded                (17 KB)
//   Vs[64][64]   V row-major                         (16 KB)
//   Pd[64][128]  P transposed + duplicated by q-row  (32 KB)
// ---------------------------------------------------------------------------
#define KT_LD 68

__global__ void __launch_bounds__(256) attn_kernel() {
    extern __shared__ float sm[];
    float* Qd = sm;                        // 64*128
    float* Kt = Qd + 64 * 128;             // 64*68
    float* Vs = Kt + 64 * KT_LD;           // 64*64
    float* Pd = Vs + 64 * 64;              // 64*128

    int tid = threadIdx.x;
    int tx = tid & 15, ty = tid >> 4;
    int qb = blockIdx.x;
    int bh = blockIdx.y;
    int b = bh >> 4, h = bh & 15;
    int t0 = b * NSEQ;

    // Q tile, transposed + duplicated: Qd[d][2*qrow .. 2*qrow+1]
#pragma unroll
    for (int it = 0; it < 4; it++) {
        int idx = tid + it * 256;
        int r = idx >> 4, c4 = (idx & 15) << 2;
        float4 v = *(const float4*)&g_qkv[(size_t)(t0 + qb * 64 + r) * QKV_N + h * 64 + c4];
        *(float2*)&Qd[(c4 + 0) * 128 + 2 * r] = make_float2(v.x, v.x);
        *(float2*)&Qd[(c4 + 1) * 128 + 2 * r] = make_float2(v.y, v.y);
        *(float2*)&Qd[(c4 + 2) * 128 + 2 * r] = make_float2(v.z, v.z);
        *(float2*)&Qd[(c4 + 3) * 128 + 2 * r] = make_float2(v.w, v.w);
    }

    ull o2[4][2];
#pragma unroll
    for (int i = 0; i < 4; i++) { o2[i][0] = 0ull; o2[i][1] = 0ull; }
    float m_[4] = {-1e30f, -1e30f, -1e30f, -1e30f};
    float l_[4] = {0.0f, 0.0f, 0.0f, 0.0f};

    for (int kb = 0; kb <= qb; kb++) {
        __syncthreads();  // prev readers done (covers Qd fill on iter 0)
#pragma unroll
        for (int it = 0; it < 4; it++) {
            int idx = tid + it * 256;
            int r = idx >> 4, c4 = (idx & 15) << 2;
            const float* src = &g_qkv[(size_t)(t0 + kb * 64 + r) * QKV_N + DIMSZ + h * 64 + c4];
            float4 kv = *(const float4*)src;
            Kt[(c4 + 0) * KT_LD + r] = kv.x;
            Kt[(c4 + 1) * KT_LD + r] = kv.y;
            Kt[(c4 + 2) * KT_LD + r] = kv.z;
            Kt[(c4 + 3) * KT_LD + r] = kv.w;
            *(float4*)&Vs[r * 64 + c4] = *(const float4*)(src + DIMSZ);
        }
        __syncthreads();

        // S = Q K^T (packed over kv-cols)
        ull s2[4][2];
#pragma unroll
        for (int i = 0; i < 4; i++) { s2[i][0] = 0ull; s2[i][1] = 0ull; }
#pragma unroll 8
        for (int d = 0; d < 64; d++) {
            ulonglong2 qa = *(ulonglong2*)&Qd[d * 128 + ty * 8];      // (q0,q0),(q1,q1)
            ulonglong2 qb2 = *(ulonglong2*)&Qd[d * 128 + ty * 8 + 4]; // (q2,q2),(q3,q3)
            ulonglong2 kk = *(ulonglong2*)&Kt[d * KT_LD + tx * 4];    // (k0,k1),(k2,k3)
            s2[0][0] = fma2(qa.x,  kk.x, s2[0][0]); s2[0][1] = fma2(qa.x,  kk.y, s2[0][1]);
            s2[1][0] = fma2(qa.y,  kk.x, s2[1][0]); s2[1][1] = fma2(qa.y,  kk.y, s2[1][1]);
            s2[2][0] = fma2(qb2.x, kk.x, s2[2][0]); s2[2][1] = fma2(qb2.x, kk.y, s2[2][1]);
            s2[3][0] = fma2(qb2.y, kk.x, s2[3][0]); s2[3][1] = fma2(qb2.y, kk.y, s2[3][1]);
        }

        float s[4][4];
#pragma unroll
        for (int i = 0; i < 4; i++) {
            float2 lo = unpk(s2[i][0]), hi = unpk(s2[i][1]);
            s[i][0] = lo.x; s[i][1] = lo.y; s[i][2] = hi.x; s[i][3] = hi.y;
        }

        const float scale = 0.125f;
        if (kb == qb) {
#pragma unroll
            for (int i = 0; i < 4; i++)
#pragma unroll
                for (int j = 0; j < 4; j++)
                    s[i][j] = (tx * 4 + j > ty * 4 + i) ? -1e30f : s[i][j] * scale;
        } else {
#pragma unroll
            for (int i = 0; i < 4; i++)
#pragma unroll
                for (int j = 0; j < 4; j++) s[i][j] *= scale;
        }

        // Online softmax
#pragma unroll
        for (int i = 0; i < 4; i++) {
            float tm = fmaxf(fmaxf(s[i][0], s[i][1]), fmaxf(s[i][2], s[i][3]));
            tm = fmaxf(tm, __shfl_xor_sync(0xffffffffu, tm, 8));
            tm = fmaxf(tm, __shfl_xor_sync(0xffffffffu, tm, 4));
            tm = fmaxf(tm, __shfl_xor_sync(0xffffffffu, tm, 2));
            tm = fmaxf(tm, __shfl_xor_sync(0xffffffffu, tm, 1));
            float mn = fmaxf(m_[i], tm);
            float al = __expf(m_[i] - mn);
            m_[i] = mn;
            float sum = 0.0f;
#pragma unroll
            for (int j = 0; j < 4; j++) {
                s[i][j] = __expf(s[i][j] - mn);
                sum += s[i][j];
            }
            sum += __shfl_xor_sync(0xffffffffu, sum, 8);
            sum += __shfl_xor_sync(0xffffffffu, sum, 4);
            sum += __shfl_xor_sync(0xffffffffu, sum, 2);
            sum += __shfl_xor_sync(0xffffffffu, sum, 1);
            l_[i] = l_[i] * al + sum;
            ull al2 = dup2(al);
            o2[i][0] = mul2(o2[i][0], al2);
            o2[i][1] = mul2(o2[i][1], al2);
        }

        __syncthreads();  // all warps done reading Kt/prev Pd
        // P transposed + duplicated: Pd[kv][2*qrow .. +1]
#pragma unroll
        for (int j = 0; j < 4; j++) {
            int row = tx * 4 + j;
            *(float4*)&Pd[row * 128 + ty * 8]     = make_float4(s[0][j], s[0][j], s[1][j], s[1][j]);
            *(float4*)&Pd[row * 128 + ty * 8 + 4] = make_float4(s[2][j], s[2][j], s[3][j], s[3][j]);
        }
        __syncthreads();

        // O += P V (packed over d-cols)
#pragma unroll 8
        for (int j = 0; j < 64; j++) {
            ulonglong2 pa = *(ulonglong2*)&Pd[j * 128 + ty * 8];      // (p0,p0),(p1,p1)
            ulonglong2 pb = *(ulonglong2*)&Pd[j * 128 + ty * 8 + 4];  // (p2,p2),(p3,p3)
            ulonglong2 vv = *(ulonglong2*)&Vs[j * 64 + tx * 4];       // (v0,v1),(v2,v3)
            o2[0][0] = fma2(pa.x, vv.x, o2[0][0]); o2[0][1] = fma2(pa.x, vv.y, o2[0][1]);
            o2[1][0] = fma2(pa.y, vv.x, o2[1][0]); o2[1][1] = fma2(pa.y, vv.y, o2[1][1]);
            o2[2][0] = fma2(pb.x, vv.x, o2[2][0]); o2[2][1] = fma2(pb.x, vv.y, o2[2][1]);
            o2[3][0] = fma2(pb.y, vv.x, o2[3][0]); o2[3][1] = fma2(pb.y, vv.y, o2[3][1]);
        }
    }

#pragma unroll
    for (int i = 0; i < 4; i++) {
        float inv = 1.0f / l_[i];
        int tok = t0 + qb * 64 + ty * 4 + i;
        float2 a = unpk(o2[i][0]), c = unpk(o2[i][1]);
        float4 w = make_float4(a.x * inv, a.y * inv, c.x * inv, c.y * inv);
        *(float4*)&g_att[(size_t)tok * DIMSZ + h * 64 + tx * 4] = w;
    }
}

// ---------------------------------------------------------------------------
extern "C" void kernel_launch(void* const* d_in, const int* in_sizes, int n_in,
                              void* d_out, int out_size) {
    const float* x     = (const float*)d_in[0];
    const float* gamma = (const float*)d_in[1];
    const float* w_qkv = (const float*)d_in[2];
    const float* w_out = (const float*)d_in[3];
    float*       out   = (float*)d_out;
    (void)in_sizes; (void)n_in; (void)out_size;

    float *p_xn, *p_qkv, *p_att;
    cudaGetSymbolAddress((void**)&p_xn,  g_xn);
    cudaGetSymbolAddress((void**)&p_qkv, g_qkv);
    cudaGetSymbolAddress((void**)&p_att, g_att);

    const int attn_smem = (64 * 128 + 64 * KT_LD + 64 * 64 + 64 * 128) * 4;  // 99328 B
    static int attr_set = 0;
    if (!attr_set) {
        cudaFuncSetAttribute(attn_kernel, cudaFuncAttributeMaxDynamicSharedMemorySize, attn_smem);
        attr_set = 1;
    }

    rmsnorm_kernel<<<TOKENS, 256>>>(x, gamma);
    sgemm_kernel<<<dim3(QKV_N / 128, TOKENS / 128), 256>>>(p_xn, w_qkv, p_qkv, QKV_N);
    attn_kernel<<<dim3(NSEQ / 64, 2 * HEADS), 256, attn_smem>>>();
    sgemm_kernel<<<dim3(DIMSZ / 128, TOKENS / 128), 256>>>(p_att, w_out, out, DIMSZ);
}

// round 8
// speedup vs baseline: 1.5760x; 1.5760x over previous
#include <cuda_runtime.h>
#include <cuda_bf16.h>
#include <cstdint>

#define TOKENS 4096
#define DIMSZ  1024
#define NSEQ   2048
#define HEADS  16
#define QKV_N  3072

typedef __nv_bfloat16 bf16;

// Scratch (device globals per harness rules)
__device__ float g_qkv[TOKENS * QKV_N];          // fp32 QKV activations
__device__ bf16  g_xnh[TOKENS * DIMSZ];          // rmsnorm out, split hi/lo
__device__ bf16  g_xnl[TOKENS * DIMSZ];
__device__ bf16  g_wqh[QKV_N * DIMSZ];           // w_qkv^T split  [3072][1024]
__device__ bf16  g_wql[QKV_N * DIMSZ];
__device__ bf16  g_ath[TOKENS * DIMSZ];          // attention out split
__device__ bf16  g_atl[TOKENS * DIMSZ];
__device__ bf16  g_woh[DIMSZ * DIMSZ];           // w_out^T split  [1024][1024]
__device__ bf16  g_wol[DIMSZ * DIMSZ];

__device__ __forceinline__ uint32_t smem_u32(const void* p) {
    uint32_t a;
    asm("{ .reg .u64 t; cvta.to.shared.u64 t, %1; cvt.u32.u64 %0, t; }" : "=r"(a) : "l"(p));
    return a;
}

__device__ __forceinline__ void split(float v, bf16& h, bf16& l) {
    h = __float2bfloat16(v);
    l = __float2bfloat16(v - __bfloat162float(h));
}

__device__ __forceinline__ void ldsm_x4(uint32_t* r, uint32_t addr) {
    asm volatile("ldmatrix.sync.aligned.m8n8.x4.shared.b16 {%0,%1,%2,%3}, [%4];"
        : "=r"(r[0]), "=r"(r[1]), "=r"(r[2]), "=r"(r[3]) : "r"(addr));
}

__device__ __forceinline__ void mma_bf16(float* c, const uint32_t* a, uint32_t b0, uint32_t b1) {
    asm volatile(
        "mma.sync.aligned.m16n8k16.row.col.f32.bf16.bf16.f32 "
        "{%0,%1,%2,%3}, {%4,%5,%6,%7}, {%8,%9}, {%0,%1,%2,%3};"
        : "+f"(c[0]), "+f"(c[1]), "+f"(c[2]), "+f"(c[3])
        : "r"(a[0]), "r"(a[1]), "r"(a[2]), "r"(a[3]), "r"(b0), "r"(b1));
}

// ---------------------------------------------------------------------------
// RMSNorm -> split bf16 hi/lo
// ---------------------------------------------------------------------------
__global__ void __launch_bounds__(256) rmsnorm_kernel(const float* __restrict__ x,
                                                      const float* __restrict__ gamma) {
    int row = blockIdx.x;
    int tid = threadIdx.x;
    const float4 v = ((const float4*)(x + (size_t)row * DIMSZ))[tid];
    float ss = v.x * v.x + v.y * v.y + v.z * v.z + v.w * v.w;
#pragma unroll
    for (int off = 16; off >= 1; off >>= 1)
        ss += __shfl_xor_sync(0xffffffffu, ss, off);
    __shared__ float red[8];
    int lane = tid & 31, wid = tid >> 5;
    if (lane == 0) red[wid] = ss;
    __syncthreads();
    if (wid == 0) {
        float t = (lane < 8) ? red[lane] : 0.0f;
#pragma unroll
        for (int off = 4; off >= 1; off >>= 1)
            t += __shfl_xor_sync(0xffffffffu, t, off);
        if (lane == 0) red[0] = t;
    }
    __syncthreads();
    float norm = fmaxf(sqrtf(red[0]), 1e-12f);
    float scl = 32.0f / norm;
    const float4 g = ((const float4*)gamma)[tid];
    float o0 = v.x * scl * g.x, o1 = v.y * scl * g.y;
    float o2 = v.z * scl * g.z, o3 = v.w * scl * g.w;
    __align__(8) bf16 hh[4], ll[4];
    split(o0, hh[0], ll[0]); split(o1, hh[1], ll[1]);
    split(o2, hh[2], ll[2]); split(o3, hh[3], ll[3]);
    size_t off = (size_t)row * DIMSZ + tid * 4;
    *(uint2*)&g_xnh[off] = *(uint2*)hh;
    *(uint2*)&g_xnl[off] = *(uint2*)ll;
}

// ---------------------------------------------------------------------------
// Transpose + split: W[K][N] fp32 -> Th/Tl[N][K] bf16
// ---------------------------------------------------------------------------
__global__ void tsplit_kernel(const float* __restrict__ W, bf16* __restrict__ Th,
                              bf16* __restrict__ Tl, int K, int N) {
    __shared__ float s[32][33];
    int tx = threadIdx.x, ty = threadIdx.y;
    int n0 = blockIdx.x * 32, k0 = blockIdx.y * 32;
#pragma unroll
    for (int j = 0; j < 32; j += 8)
        s[ty + j][tx] = W[(size_t)(k0 + ty + j) * N + n0 + tx];
    __syncthreads();
#pragma unroll
    for (int j = 0; j < 32; j += 8) {
        float v = s[tx][ty + j];
        bf16 h, l; split(v, h, l);
        size_t o = (size_t)(n0 + ty + j) * K + k0 + tx;
        Th[o] = h; Tl[o] = l;
    }
}

// ---------------------------------------------------------------------------
// Split-bf16 mma.sync GEMM: C[M,N] = A[M,1024] @ Bt[N,1024]^T
//   C ~= Ah·Bh + Ah·Bl + Al·Bh   (fp32 accumulators)
// 128x128 CTA tile, 8 warps as 2x4 grid of 64x32 warp tiles, K-slab 32.
// Smem rows padded to 40 bf16 (80B stride) -> conflict-free ldmatrix.
// ---------------------------------------------------------------------------
#define SPITCH 40

__global__ void __launch_bounds__(256) gemm_mma(const bf16* __restrict__ Ah, const bf16* __restrict__ Al,
                                                const bf16* __restrict__ Bh, const bf16* __restrict__ Bl,
                                                float* __restrict__ C, int N) {
    __shared__ __align__(16) bf16 sAh[128 * SPITCH];
    __shared__ __align__(16) bf16 sAl[128 * SPITCH];
    __shared__ __align__(16) bf16 sBh[128 * SPITCH];
    __shared__ __align__(16) bf16 sBl[128 * SPITCH];

    int tid = threadIdx.x, lane = tid & 31, wid = tid >> 5;
    int wm = wid >> 2, wn = wid & 3;          // warp tile (64m x 32n)
    int bm = blockIdx.y * 128, bn = blockIdx.x * 128;

    // ldmatrix lane address bases
    int rowA = wm * 64 + (lane & 7) + ((lane >> 3) & 1) * 8;
    int koffA = (lane >> 4) * 8;
    uint32_t aHb = smem_u32(sAh) + (uint32_t)(rowA * SPITCH + koffA) * 2;
    uint32_t aLb = smem_u32(sAl) + (uint32_t)(rowA * SPITCH + koffA) * 2;
    int nrow = wn * 32 + (lane & 7) + ((lane >> 4) & 1) * 8;
    int koffB = ((lane >> 3) & 1) * 8;
    uint32_t bHb = smem_u32(sBh) + (uint32_t)(nrow * SPITCH + koffB) * 2;
    uint32_t bLb = smem_u32(sBl) + (uint32_t)(nrow * SPITCH + koffB) * 2;

    float c[4][4][4];
#pragma unroll
    for (int i = 0; i < 4; i++)
#pragma unroll
        for (int j = 0; j < 4; j++)
#pragma unroll
            for (int k = 0; k < 4; k++) c[i][j][k] = 0.0f;

    // initial slab 0 -> smem
#pragma unroll
    for (int t = 0; t < 2; t++) {
        int idx = tid + t * 256;
        int row = idx >> 2, cc = (idx & 3) * 8;
        *(float4*)&sAh[row * SPITCH + cc] = *(const float4*)(Ah + (size_t)(bm + row) * DIMSZ + cc);
        *(float4*)&sAl[row * SPITCH + cc] = *(const float4*)(Al + (size_t)(bm + row) * DIMSZ + cc);
        *(float4*)&sBh[row * SPITCH + cc] = *(const float4*)(Bh + (size_t)(bn + row) * DIMSZ + cc);
        *(float4*)&sBl[row * SPITCH + cc] = *(const float4*)(Bl + (size_t)(bn + row) * DIMSZ + cc);
    }
    __syncthreads();

    const int NSLAB = DIMSZ / 32;  // 32
    for (int s = 0; s < NSLAB; s++) {
        float4 pa[2], pl[2], pb[2], pm[2];
        if (s < NSLAB - 1) {
            int k0 = (s + 1) * 32;
#pragma unroll
            for (int t = 0; t < 2; t++) {
                int idx = tid + t * 256;
                int row = idx >> 2, cc = (idx & 3) * 8;
                pa[t] = *(const float4*)(Ah + (size_t)(bm + row) * DIMSZ + k0 + cc);
                pl[t] = *(const float4*)(Al + (size_t)(bm + row) * DIMSZ + k0 + cc);
                pb[t] = *(const float4*)(Bh + (size_t)(bn + row) * DIMSZ + k0 + cc);
                pm[t] = *(const float4*)(Bl + (size_t)(bn + row) * DIMSZ + k0 + cc);
            }
        }
#pragma unroll
        for (int kk = 0; kk < 2; kk++) {
            uint32_t ko = kk * 32;  // 16 bf16 * 2B
            uint32_t aH[4][4], aL[4][4], bH[2][4], bL[2][4];
#pragma unroll
            for (int mt = 0; mt < 4; mt++) {
                ldsm_x4(aH[mt], aHb + mt * (16 * SPITCH * 2) + ko);
                ldsm_x4(aL[mt], aLb + mt * (16 * SPITCH * 2) + ko);
            }
#pragma unroll
            for (int pr = 0; pr < 2; pr++) {
                ldsm_x4(bH[pr], bHb + pr * (16 * SPITCH * 2) + ko);
                ldsm_x4(bL[pr], bLb + pr * (16 * SPITCH * 2) + ko);
            }
#pragma unroll
            for (int mt = 0; mt < 4; mt++)
#pragma unroll
                for (int nt = 0; nt < 4; nt++) {
                    int pr = nt >> 1, hf = (nt & 1) * 2;
                    mma_bf16(c[mt][nt], aH[mt], bH[pr][hf], bH[pr][hf + 1]);
                    mma_bf16(c[mt][nt], aH[mt], bL[pr][hf], bL[pr][hf + 1]);
                    mma_bf16(c[mt][nt], aL[mt], bH[pr][hf], bH[pr][hf + 1]);
                }
        }
        __syncthreads();
        if (s < NSLAB - 1) {
#pragma unroll
            for (int t = 0; t < 2; t++) {
                int idx = tid + t * 256;
                int row = idx >> 2, cc = (idx & 3) * 8;
                *(float4*)&sAh[row * SPITCH + cc] = pa[t];
                *(float4*)&sAl[row * SPITCH + cc] = pl[t];
                *(float4*)&sBh[row * SPITCH + cc] = pb[t];
                *(float4*)&sBl[row * SPITCH + cc] = pm[t];
            }
            __syncthreads();
        }
    }

    // epilogue: fragment (m16n8) thread map: c0,c1 @ (lane>>2, (lane&3)*2); c2,c3 @ +8 rows
#pragma unroll
    for (int mt = 0; mt < 4; mt++)
#pragma unroll
        for (int nt = 0; nt < 4; nt++) {
            int r0 = bm + wm * 64 + mt * 16 + (lane >> 2);
            int col = bn + wn * 32 + nt * 8 + (lane & 3) * 2;
            *(float2*)&C[(size_t)r0 * N + col]       = make_float2(c[mt][nt][0], c[mt][nt][1]);
            *(float2*)&C[(size_t)(r0 + 8) * N + col] = make_float2(c[mt][nt][2], c[mt][nt][3]);
        }
}

// ---------------------------------------------------------------------------
// Causal flash attention, fp32 (R3 version; epilogue emits split bf16)
// ---------------------------------------------------------------------------
__global__ void __launch_bounds__(256) attn_kernel() {
    __shared__ float Qt [64 * 64];
    __shared__ float KPt[64 * 64];
    __shared__ float Vs [64 * 64];

    int tid = threadIdx.x;
    int tx = tid & 15, ty = tid >> 4;
    int qb = blockIdx.x;
    int bh = blockIdx.y;
    int b = bh >> 4, h = bh & 15;
    int t0 = b * NSEQ;

#pragma unroll
    for (int it = 0; it < 4; it++) {
        int idx = tid + it * 256;
        int r = idx >> 4, c4 = (idx & 15) << 2;
        float4 v = *(const float4*)&g_qkv[(size_t)(t0 + qb * 64 + r) * QKV_N + h * 64 + c4];
        Qt[(c4 + 0) * 64 + r] = v.x;
        Qt[(c4 + 1) * 64 + r] = v.y;
        Qt[(c4 + 2) * 64 + r] = v.z;
        Qt[(c4 + 3) * 64 + r] = v.w;
    }

    float o[4][4];
#pragma unroll
    for (int i = 0; i < 4; i++)
#pragma unroll
        for (int j = 0; j < 4; j++) o[i][j] = 0.0f;
    float m_[4] = {-1e30f, -1e30f, -1e30f, -1e30f};
    float l_[4] = {0.0f, 0.0f, 0.0f, 0.0f};

    for (int kb = 0; kb <= qb; kb++) {
        __syncthreads();
#pragma unroll
        for (int it = 0; it < 4; it++) {
            int idx = tid + it * 256;
            int r = idx >> 4, c4 = (idx & 15) << 2;
            const float* src = &g_qkv[(size_t)(t0 + kb * 64 + r) * QKV_N + DIMSZ + h * 64 + c4];
            float4 kv = *(const float4*)src;
            KPt[(c4 + 0) * 64 + r] = kv.x;
            KPt[(c4 + 1) * 64 + r] = kv.y;
            KPt[(c4 + 2) * 64 + r] = kv.z;
            KPt[(c4 + 3) * 64 + r] = kv.w;
            *(float4*)&Vs[r * 64 + c4] = *(const float4*)(src + DIMSZ);
        }
        __syncthreads();

        float s[4][4];
#pragma unroll
        for (int i = 0; i < 4; i++)
#pragma unroll
            for (int j = 0; j < 4; j++) s[i][j] = 0.0f;
#pragma unroll 8
        for (int d = 0; d < 64; d++) {
            float4 q  = *(float4*)&Qt [d * 64 + ty * 4];
            float4 kk = *(float4*)&KPt[d * 64 + tx * 4];
            s[0][0] += q.x * kk.x; s[0][1] += q.x * kk.y; s[0][2] += q.x * kk.z; s[0][3] += q.x * kk.w;
            s[1][0] += q.y * kk.x; s[1][1] += q.y * kk.y; s[1][2] += q.y * kk.z; s[1][3] += q.y * kk.w;
            s[2][0] += q.z * kk.x; s[2][1] += q.z * kk.y; s[2][2] += q.z * kk.z; s[2][3] += q.z * kk.w;
            s[3][0] += q.w * kk.x; s[3][1] += q.w * kk.y; s[3][2] += q.w * kk.z; s[3][3] += q.w * kk.w;
        }
        const float scale = 0.125f;
        if (kb == qb) {
#pragma unroll
            for (int i = 0; i < 4; i++)
#pragma unroll
                for (int j = 0; j < 4; j++)
                    s[i][j] = (tx * 4 + j > ty * 4 + i) ? -1e30f : s[i][j] * scale;
        } else {
#pragma unroll
            for (int i = 0; i < 4; i++)
#pragma unroll
                for (int j = 0; j < 4; j++) s[i][j] *= scale;
        }

#pragma unroll
        for (int i = 0; i < 4; i++) {
            float tm = fmaxf(fmaxf(s[i][0], s[i][1]), fmaxf(s[i][2], s[i][3]));
            tm = fmaxf(tm, __shfl_xor_sync(0xffffffffu, tm, 8));
            tm = fmaxf(tm, __shfl_xor_sync(0xffffffffu, tm, 4));
            tm = fmaxf(tm, __shfl_xor_sync(0xffffffffu, tm, 2));
            tm = fmaxf(tm, __shfl_xor_sync(0xffffffffu, tm, 1));
            float mn = fmaxf(m_[i], tm);
            float al = __expf(m_[i] - mn);
            m_[i] = mn;
            float sum = 0.0f;
#pragma unroll
            for (int j = 0; j < 4; j++) {
                s[i][j] = __expf(s[i][j] - mn);
                sum += s[i][j];
            }
            sum += __shfl_xor_sync(0xffffffffu, sum, 8);
            sum += __shfl_xor_sync(0xffffffffu, sum, 4);
            sum += __shfl_xor_sync(0xffffffffu, sum, 2);
            sum += __shfl_xor_sync(0xffffffffu, sum, 1);
            l_[i] = l_[i] * al + sum;
#pragma unroll
            for (int cc = 0; cc < 4; cc++) o[i][cc] *= al;
        }

        __syncthreads();
#pragma unroll
        for (int j = 0; j < 4; j++) {
            float4 w = make_float4(s[0][j], s[1][j], s[2][j], s[3][j]);
            *(float4*)&KPt[(tx * 4 + j) * 64 + ty * 4] = w;
        }
        __syncthreads();

#pragma unroll 8
        for (int j = 0; j < 64; j++) {
            float4 p4 = *(float4*)&KPt[j * 64 + ty * 4];
            float4 v4 = *(float4*)&Vs [j * 64 + tx * 4];
            o[0][0] += p4.x * v4.x; o[0][1] += p4.x * v4.y; o[0][2] += p4.x * v4.z; o[0][3] += p4.x * v4.w;
            o[1][0] += p4.y * v4.x; o[1][1] += p4.y * v4.y; o[1][2] += p4.y * v4.z; o[1][3] += p4.y * v4.w;
            o[2][0] += p4.z * v4.x; o[2][1] += p4.z * v4.y; o[2][2] += p4.z * v4.z; o[2][3] += p4.z * v4.w;
            o[3][0] += p4.w * v4.x; o[3][1] += p4.w * v4.y; o[3][2] += p4.w * v4.z; o[3][3] += p4.w * v4.w;
        }
    }

#pragma unroll
    for (int i = 0; i < 4; i++) {
        float inv = 1.0f / l_[i];
        int tok = t0 + qb * 64 + ty * 4 + i;
        float v0 = o[i][0] * inv, v1 = o[i][1] * inv, v2 = o[i][2] * inv, v3 = o[i][3] * inv;
        __align__(8) bf16 hh[4], ll[4];
        split(v0, hh[0], ll[0]); split(v1, hh[1], ll[1]);
        split(v2, hh[2], ll[2]); split(v3, hh[3], ll[3]);
        size_t off = (size_t)tok * DIMSZ + h * 64 + tx * 4;
        *(uint2*)&g_ath[off] = *(uint2*)hh;
        *(uint2*)&g_atl[off] = *(uint2*)ll;
    }
}

// ---------------------------------------------------------------------------
extern "C" void kernel_launch(void* const* d_in, const int* in_sizes, int n_in,
                              void* d_out, int out_size) {
    const float* x     = (const float*)d_in[0];
    const float* gamma = (const float*)d_in[1];
    const float* w_qkv = (const float*)d_in[2];
    const float* w_out = (const float*)d_in[3];
    float*       out   = (float*)d_out;
    (void)in_sizes; (void)n_in; (void)out_size;

    float* p_qkv;
    bf16 *p_xnh, *p_xnl, *p_wqh, *p_wql, *p_ath, *p_atl, *p_woh, *p_wol;
    cudaGetSymbolAddress((void**)&p_qkv, g_qkv);
    cudaGetSymbolAddress((void**)&p_xnh, g_xnh);
    cudaGetSymbolAddress((void**)&p_xnl, g_xnl);
    cudaGetSymbolAddress((void**)&p_wqh, g_wqh);
    cudaGetSymbolAddress((void**)&p_wql, g_wql);
    cudaGetSymbolAddress((void**)&p_ath, g_ath);
    cudaGetSymbolAddress((void**)&p_atl, g_atl);
    cudaGetSymbolAddress((void**)&p_woh, g_woh);
    cudaGetSymbolAddress((void**)&p_wol, g_wol);

    rmsnorm_kernel<<<TOKENS, 256>>>(x, gamma);
    tsplit_kernel<<<dim3(QKV_N / 32, DIMSZ / 32), dim3(32, 8)>>>(w_qkv, p_wqh, p_wql, DIMSZ, QKV_N);
    tsplit_kernel<<<dim3(DIMSZ / 32, DIMSZ / 32), dim3(32, 8)>>>(w_out, p_woh, p_wol, DIMSZ, DIMSZ);
    gemm_mma<<<dim3(QKV_N / 128, TOKENS / 128), 256>>>(p_xnh, p_xnl, p_wqh, p_wql, p_qkv, QKV_N);
    attn_kernel<<<dim3(NSEQ / 64, 2 * HEADS), 256>>>();
    gemm_mma<<<dim3(DIMSZ / 128, TOKENS / 128), 256>>>(p_ath, p_atl, p_woh, p_wol, out, DIMSZ);
}

// round 10
// speedup vs baseline: 2.9453x; 1.8689x over previous
#include <cuda_runtime.h>
#include <cuda_bf16.h>
#include <cstdint>

#define TOKENS 4096
#define DIMSZ  1024
#define NSEQ   2048
#define HEADS  16
#define QKV_N  3072

typedef __nv_bfloat16 bf16;

// Scratch (device globals per harness rules)
__device__ float g_qkv[TOKENS * QKV_N];          // fp32 QKV activations
__device__ bf16  g_xnh[TOKENS * DIMSZ];          // rmsnorm out, split hi/lo
__device__ bf16  g_xnl[TOKENS * DIMSZ];
__device__ bf16  g_wqh[QKV_N * DIMSZ];           // w_qkv^T split  [3072][1024]
__device__ bf16  g_wql[QKV_N * DIMSZ];
__device__ bf16  g_ath[TOKENS * DIMSZ];          // attention out split
__device__ bf16  g_atl[TOKENS * DIMSZ];
__device__ bf16  g_woh[DIMSZ * DIMSZ];           // w_out^T split  [1024][1024]
__device__ bf16  g_wol[DIMSZ * DIMSZ];

__device__ __forceinline__ uint32_t smem_u32(const void* p) {
    uint32_t a;
    asm("{ .reg .u64 t; cvta.to.shared.u64 t, %1; cvt.u32.u64 %0, t; }" : "=r"(a) : "l"(p));
    return a;
}

__device__ __forceinline__ void split(float v, bf16& h, bf16& l) {
    h = __float2bfloat16(v);
    l = __float2bfloat16(v - __bfloat162float(h));
}

__device__ __forceinline__ void ldsm_x4(uint32_t* r, uint32_t addr) {
    asm volatile("ldmatrix.sync.aligned.m8n8.x4.shared.b16 {%0,%1,%2,%3}, [%4];"
        : "=r"(r[0]), "=r"(r[1]), "=r"(r[2]), "=r"(r[3]) : "r"(addr));
}

__device__ __forceinline__ void ldsm_x4_t(uint32_t* r, uint32_t addr) {
    asm volatile("ldmatrix.sync.aligned.m8n8.x4.trans.shared.b16 {%0,%1,%2,%3}, [%4];"
        : "=r"(r[0]), "=r"(r[1]), "=r"(r[2]), "=r"(r[3]) : "r"(addr));
}

__device__ __forceinline__ void mma_bf16(float* c, const uint32_t* a, uint32_t b0, uint32_t b1) {
    asm volatile(
        "mma.sync.aligned.m16n8k16.row.col.f32.bf16.bf16.f32 "
        "{%0,%1,%2,%3}, {%4,%5,%6,%7}, {%8,%9}, {%0,%1,%2,%3};"
        : "+f"(c[0]), "+f"(c[1]), "+f"(c[2]), "+f"(c[3])
        : "r"(a[0]), "r"(a[1]), "r"(a[2]), "r"(a[3]), "r"(b0), "r"(b1));
}

// pack (x,y) into bf16x2 hi-part and residual lo-part registers (x -> low 16 bits)
__device__ __forceinline__ void psplit2(float x, float y, uint32_t& ph, uint32_t& pl) {
    bf16 hx = __float2bfloat16(x), hy = __float2bfloat16(y);
    bf16 lx = __float2bfloat16(x - __bfloat162float(hx));
    bf16 ly = __float2bfloat16(y - __bfloat162float(hy));
    ph = ((uint32_t)__bfloat16_as_ushort(hy) << 16) | __bfloat16_as_ushort(hx);
    pl = ((uint32_t)__bfloat16_as_ushort(ly) << 16) | __bfloat16_as_ushort(lx);
}

// ---------------------------------------------------------------------------
// RMSNorm -> split bf16 hi/lo
// ---------------------------------------------------------------------------
__global__ void __launch_bounds__(256) rmsnorm_kernel(const float* __restrict__ x,
                                                      const float* __restrict__ gamma) {
    int row = blockIdx.x;
    int tid = threadIdx.x;
    const float4 v = ((const float4*)(x + (size_t)row * DIMSZ))[tid];
    float ss = v.x * v.x + v.y * v.y + v.z * v.z + v.w * v.w;
#pragma unroll
    for (int off = 16; off >= 1; off >>= 1)
        ss += __shfl_xor_sync(0xffffffffu, ss, off);
    __shared__ float red[8];
    int lane = tid & 31, wid = tid >> 5;
    if (lane == 0) red[wid] = ss;
    __syncthreads();
    if (wid == 0) {
        float t = (lane < 8) ? red[lane] : 0.0f;
#pragma unroll
        for (int off = 4; off >= 1; off >>= 1)
            t += __shfl_xor_sync(0xffffffffu, t, off);
        if (lane == 0) red[0] = t;
    }
    __syncthreads();
    float norm = fmaxf(sqrtf(red[0]), 1e-12f);
    float scl = 32.0f / norm;
    const float4 g = ((const float4*)gamma)[tid];
    float o0 = v.x * scl * g.x, o1 = v.y * scl * g.y;
    float o2 = v.z * scl * g.z, o3 = v.w * scl * g.w;
    __align__(8) bf16 hh[4], ll[4];
    split(o0, hh[0], ll[0]); split(o1, hh[1], ll[1]);
    split(o2, hh[2], ll[2]); split(o3, hh[3], ll[3]);
    size_t off = (size_t)row * DIMSZ + tid * 4;
    *(uint2*)&g_xnh[off] = *(uint2*)hh;
    *(uint2*)&g_xnl[off] = *(uint2*)ll;
}

// ---------------------------------------------------------------------------
// Transpose + split: W[K][N] fp32 -> Th/Tl[N][K] bf16
// ---------------------------------------------------------------------------
__global__ void tsplit_kernel(const float* __restrict__ W, bf16* __restrict__ Th,
                              bf16* __restrict__ Tl, int K, int N) {
    __shared__ float s[32][33];
    int tx = threadIdx.x, ty = threadIdx.y;
    int n0 = blockIdx.x * 32, k0 = blockIdx.y * 32;
#pragma unroll
    for (int j = 0; j < 32; j += 8)
        s[ty + j][tx] = W[(size_t)(k0 + ty + j) * N + n0 + tx];
    __syncthreads();
#pragma unroll
    for (int j = 0; j < 32; j += 8) {
        float v = s[tx][ty + j];
        bf16 h, l; split(v, h, l);
        size_t o = (size_t)(n0 + ty + j) * K + k0 + tx;
        Th[o] = h; Tl[o] = l;
    }
}

// ---------------------------------------------------------------------------
// Split-bf16 mma.sync GEMM: C[M,N] = A[M,1024] @ Bt[N,1024]^T
// (unchanged from R7 — 128x128 CTA tile, 8 warps, K-slab 32)
// ---------------------------------------------------------------------------
#define SPITCH 40

__global__ void __launch_bounds__(256) gemm_mma(const bf16* __restrict__ Ah, const bf16* __restrict__ Al,
                                                const bf16* __restrict__ Bh, const bf16* __restrict__ Bl,
                                                float* __restrict__ C, int N) {
    __shared__ __align__(16) bf16 sAh[128 * SPITCH];
    __shared__ __align__(16) bf16 sAl[128 * SPITCH];
    __shared__ __align__(16) bf16 sBh[128 * SPITCH];
    __shared__ __align__(16) bf16 sBl[128 * SPITCH];

    int tid = threadIdx.x, lane = tid & 31, wid = tid >> 5;
    int wm = wid >> 2, wn = wid & 3;
    int bm = blockIdx.y * 128, bn = blockIdx.x * 128;

    int rowA = wm * 64 + (lane & 7) + ((lane >> 3) & 1) * 8;
    int koffA = (lane >> 4) * 8;
    uint32_t aHb = smem_u32(sAh) + (uint32_t)(rowA * SPITCH + koffA) * 2;
    uint32_t aLb = smem_u32(sAl) + (uint32_t)(rowA * SPITCH + koffA) * 2;
    int nrow = wn * 32 + (lane & 7) + ((lane >> 4) & 1) * 8;
    int koffB = ((lane >> 3) & 1) * 8;
    uint32_t bHb = smem_u32(sBh) + (uint32_t)(nrow * SPITCH + koffB) * 2;
    uint32_t bLb = smem_u32(sBl) + (uint32_t)(nrow * SPITCH + koffB) * 2;

    float c[4][4][4];
#pragma unroll
    for (int i = 0; i < 4; i++)
#pragma unroll
        for (int j = 0; j < 4; j++)
#pragma unroll
            for (int k = 0; k < 4; k++) c[i][j][k] = 0.0f;

#pragma unroll
    for (int t = 0; t < 2; t++) {
        int idx = tid + t * 256;
        int row = idx >> 2, cc = (idx & 3) * 8;
        *(float4*)&sAh[row * SPITCH + cc] = *(const float4*)(Ah + (size_t)(bm + row) * DIMSZ + cc);
        *(float4*)&sAl[row * SPITCH + cc] = *(const float4*)(Al + (size_t)(bm + row) * DIMSZ + cc);
        *(float4*)&sBh[row * SPITCH + cc] = *(const float4*)(Bh + (size_t)(bn + row) * DIMSZ + cc);
        *(float4*)&sBl[row * SPITCH + cc] = *(const float4*)(Bl + (size_t)(bn + row) * DIMSZ + cc);
    }
    __syncthreads();

    const int NSLAB = DIMSZ / 32;
    for (int s = 0; s < NSLAB; s++) {
        float4 pa[2], pl[2], pb[2], pm[2];
        if (s < NSLAB - 1) {
            int k0 = (s + 1) * 32;
#pragma unroll
            for (int t = 0; t < 2; t++) {
                int idx = tid + t * 256;
                int row = idx >> 2, cc = (idx & 3) * 8;
                pa[t] = *(const float4*)(Ah + (size_t)(bm + row) * DIMSZ + k0 + cc);
                pl[t] = *(const float4*)(Al + (size_t)(bm + row) * DIMSZ + k0 + cc);
                pb[t] = *(const float4*)(Bh + (size_t)(bn + row) * DIMSZ + k0 + cc);
                pm[t] = *(const float4*)(Bl + (size_t)(bn + row) * DIMSZ + k0 + cc);
            }
        }
#pragma unroll
        for (int kk = 0; kk < 2; kk++) {
            uint32_t ko = kk * 32;
            uint32_t aH[4][4], aL[4][4], bH[2][4], bL[2][4];
#pragma unroll
            for (int mt = 0; mt < 4; mt++) {
                ldsm_x4(aH[mt], aHb + mt * (16 * SPITCH * 2) + ko);
                ldsm_x4(aL[mt], aLb + mt * (16 * SPITCH * 2) + ko);
            }
#pragma unroll
            for (int pr = 0; pr < 2; pr++) {
                ldsm_x4(bH[pr], bHb + pr * (16 * SPITCH * 2) + ko);
                ldsm_x4(bL[pr], bLb + pr * (16 * SPITCH * 2) + ko);
            }
#pragma unroll
            for (int mt = 0; mt < 4; mt++)
#pragma unroll
                for (int nt = 0; nt < 4; nt++) {
                    int pr = nt >> 1, hf = (nt & 1) * 2;
                    mma_bf16(c[mt][nt], aH[mt], bH[pr][hf], bH[pr][hf + 1]);
                    mma_bf16(c[mt][nt], aH[mt], bL[pr][hf], bL[pr][hf + 1]);
                    mma_bf16(c[mt][nt], aL[mt], bH[pr][hf], bH[pr][hf + 1]);
                }
        }
        __syncthreads();
        if (s < NSLAB - 1) {
#pragma unroll
            for (int t = 0; t < 2; t++) {
                int idx = tid + t * 256;
                int row = idx >> 2, cc = (idx & 3) * 8;
                *(float4*)&sAh[row * SPITCH + cc] = pa[t];
                *(float4*)&sAl[row * SPITCH + cc] = pl[t];
                *(float4*)&sBh[row * SPITCH + cc] = pb[t];
                *(float4*)&sBl[row * SPITCH + cc] = pm[t];
            }
            __syncthreads();
        }
    }

#pragma unroll
    for (int mt = 0; mt < 4; mt++)
#pragma unroll
        for (int nt = 0; nt < 4; nt++) {
            int r0 = bm + wm * 64 + mt * 16 + (lane >> 2);
            int col = bn + wn * 32 + nt * 8 + (lane & 3) * 2;
            *(float2*)&C[(size_t)r0 * N + col]       = make_float2(c[mt][nt][0], c[mt][nt][1]);
            *(float2*)&C[(size_t)(r0 + 8) * N + col] = make_float2(c[mt][nt][2], c[mt][nt][3]);
        }
}

// ---------------------------------------------------------------------------
// Causal flash attention via split-bf16 mma.sync.
// CTA = 128 threads (4 warps), q-block 64 rows; warp w owns rows w*16..+15.
// K/V split to bf16 hi/lo in smem each kv block; Q fragments cached in regs.
// S = Qh·Kh + Qh·Kl + Ql·Kh ; O = Ph·Vh + Pl·Vh + Ph·Vl (fp32 accum).
// ---------------------------------------------------------------------------
#define AP 72   // smem pitch (bf16) for 64-wide tiles

__global__ void __launch_bounds__(128) attn_mma() {
    __shared__ __align__(16) bf16 sKh[64 * AP];
    __shared__ __align__(16) bf16 sKl[64 * AP];
    __shared__ __align__(16) bf16 sVh[64 * AP];
    __shared__ __align__(16) bf16 sVl[64 * AP];

    int tid = threadIdx.x, lane = tid & 31, w = tid >> 5;
    int qb = blockIdx.x, bh = blockIdx.y;
    int b = bh >> 4, h = bh & 15;
    int t0 = b * NSEQ;

    // ---- stage Q (pre-scaled, split) through K buffers; build A fragments ----
#pragma unroll
    for (int i = 0; i < 8; i++) {
        int idx = tid + i * 128;
        int r = idx >> 4, c4 = (idx & 15) << 2;
        float4 v = *(const float4*)&g_qkv[(size_t)(t0 + qb * 64 + r) * QKV_N + h * 64 + c4];
        v.x *= 0.125f; v.y *= 0.125f; v.z *= 0.125f; v.w *= 0.125f;
        __align__(8) bf16 hh[4], ll[4];
        split(v.x, hh[0], ll[0]); split(v.y, hh[1], ll[1]);
        split(v.z, hh[2], ll[2]); split(v.w, hh[3], ll[3]);
        *(uint2*)&sKh[r * AP + c4] = *(uint2*)hh;
        *(uint2*)&sKl[r * AP + c4] = *(uint2*)ll;
    }
    __syncthreads();
    uint32_t qh[4][4], ql[4][4];
    {
        int rowA = w * 16 + (lane & 7) + ((lane >> 3) & 1) * 8;
        int koffA = (lane >> 4) * 8;
        uint32_t aHb = smem_u32(sKh) + (uint32_t)(rowA * AP + koffA) * 2;
        uint32_t aLb = smem_u32(sKl) + (uint32_t)(rowA * AP + koffA) * 2;
#pragma unroll
        for (int k = 0; k < 4; k++) {
            ldsm_x4(qh[k], aHb + k * 32);
            ldsm_x4(ql[k], aLb + k * 32);
        }
    }

    float o[8][4];
#pragma unroll
    for (int j = 0; j < 8; j++)
#pragma unroll
        for (int v = 0; v < 4; v++) o[j][v] = 0.0f;
    float m0 = -1e30f, m1 = -1e30f, l0 = 0.0f, l1 = 0.0f;

    int nrowB = (lane & 7) + ((lane >> 4) & 1) * 8;
    int koffB = ((lane >> 3) & 1) * 8;
    uint32_t kHb = smem_u32(sKh) + (uint32_t)(nrowB * AP + koffB) * 2;
    uint32_t kLb = smem_u32(sKl) + (uint32_t)(nrowB * AP + koffB) * 2;
    uint32_t vHb = smem_u32(sVh) + (uint32_t)((lane & 15) * AP + ((lane >> 4) & 1) * 8) * 2;
    uint32_t vLb = smem_u32(sVl) + (uint32_t)((lane & 15) * AP + ((lane >> 4) & 1) * 8) * 2;

    for (int kb = 0; kb <= qb; kb++) {
        __syncthreads();   // prior compute done (also covers Q staging on iter 0)
        // load K, V tiles (fp32 -> split bf16), row-major [kv][dh]
#pragma unroll
        for (int i = 0; i < 8; i++) {
            int idx = tid + i * 128;
            int r = idx >> 4, c4 = (idx & 15) << 2;
            const float* src = &g_qkv[(size_t)(t0 + kb * 64 + r) * QKV_N + DIMSZ + h * 64 + c4];
            float4 kv = *(const float4*)src;
            float4 vv = *(const float4*)(src + DIMSZ);
            __align__(8) bf16 hh[4], ll[4];
            split(kv.x, hh[0], ll[0]); split(kv.y, hh[1], ll[1]);
            split(kv.z, hh[2], ll[2]); split(kv.w, hh[3], ll[3]);
            *(uint2*)&sKh[r * AP + c4] = *(uint2*)hh;
            *(uint2*)&sKl[r * AP + c4] = *(uint2*)ll;
            split(vv.x, hh[0], ll[0]); split(vv.y, hh[1], ll[1]);
            split(vv.z, hh[2], ll[2]); split(vv.w, hh[3], ll[3]);
            *(uint2*)&sVh[r * AP + c4] = *(uint2*)hh;
            *(uint2*)&sVl[r * AP + c4] = *(uint2*)ll;
        }
        __syncthreads();

        // ---- S = Q K^T ----
        float s[8][4];
#pragma unroll
        for (int j = 0; j < 8; j++)
#pragma unroll
            for (int v = 0; v < 4; v++) s[j][v] = 0.0f;
#pragma unroll
        for (int k = 0; k < 4; k++)
#pragma unroll
            for (int pr = 0; pr < 4; pr++) {
                uint32_t bh_[4], bl_[4];
                ldsm_x4(bh_, kHb + pr * (16 * AP * 2) + k * 32);
                ldsm_x4(bl_, kLb + pr * (16 * AP * 2) + k * 32);
                mma_bf16(s[2 * pr],     qh[k], bh_[0], bh_[1]);
                mma_bf16(s[2 * pr],     qh[k], bl_[0], bl_[1]);
                mma_bf16(s[2 * pr],     ql[k], bh_[0], bh_[1]);
                mma_bf16(s[2 * pr + 1], qh[k], bh_[2], bh_[3]);
                mma_bf16(s[2 * pr + 1], qh[k], bl_[2], bl_[3]);
                mma_bf16(s[2 * pr + 1], ql[k], bh_[2], bh_[3]);
            }

        // causal mask on diagonal block
        int r0 = w * 16 + (lane >> 2);
        int cb = (lane & 3) * 2;
        if (kb == qb) {
#pragma unroll
            for (int j = 0; j < 8; j++) {
                int c0 = 8 * j + cb;
                if (c0     > r0    ) s[j][0] = -1e30f;
                if (c0 + 1 > r0    ) s[j][1] = -1e30f;
                if (c0     > r0 + 8) s[j][2] = -1e30f;
                if (c0 + 1 > r0 + 8) s[j][3] = -1e30f;
            }
        }

        // ---- online softmax (2 rows per thread) ----
        float tm0 = -1e30f, tm1 = -1e30f;
#pragma unroll
        for (int j = 0; j < 8; j++) {
            tm0 = fmaxf(tm0, fmaxf(s[j][0], s[j][1]));
            tm1 = fmaxf(tm1, fmaxf(s[j][2], s[j][3]));
        }
        tm0 = fmaxf(tm0, __shfl_xor_sync(0xffffffffu, tm0, 1));
        tm0 = fmaxf(tm0, __shfl_xor_sync(0xffffffffu, tm0, 2));
        tm1 = fmaxf(tm1, __shfl_xor_sync(0xffffffffu, tm1, 1));
        tm1 = fmaxf(tm1, __shfl_xor_sync(0xffffffffu, tm1, 2));
        float mn0 = fmaxf(m0, tm0), mn1 = fmaxf(m1, tm1);
        float al0 = __expf(m0 - mn0), al1 = __expf(m1 - mn1);
        m0 = mn0; m1 = mn1;
        float sum0 = 0.0f, sum1 = 0.0f;
#pragma unroll
        for (int j = 0; j < 8; j++) {
            s[j][0] = __expf(s[j][0] - mn0); sum0 += s[j][0];
            s[j][1] = __expf(s[j][1] - mn0); sum0 += s[j][1];
            s[j][2] = __expf(s[j][2] - mn1); sum1 += s[j][2];
            s[j][3] = __expf(s[j][3] - mn1); sum1 += s[j][3];
        }
        sum0 += __shfl_xor_sync(0xffffffffu, sum0, 1);
        sum0 += __shfl_xor_sync(0xffffffffu, sum0, 2);
        sum1 += __shfl_xor_sync(0xffffffffu, sum1, 1);
        sum1 += __shfl_xor_sync(0xffffffffu, sum1, 2);
        l0 = l0 * al0 + sum0;
        l1 = l1 * al1 + sum1;
#pragma unroll
        for (int j = 0; j < 8; j++) {
            o[j][0] *= al0; o[j][1] *= al0;
            o[j][2] *= al1; o[j][3] *= al1;
        }

        // ---- O += P V ----
#pragma unroll
        for (int kk = 0; kk < 4; kk++) {
            uint32_t ph[4], pl[4];
            psplit2(s[2 * kk][0],     s[2 * kk][1],     ph[0], pl[0]);
            psplit2(s[2 * kk][2],     s[2 * kk][3],     ph[1], pl[1]);
            psplit2(s[2 * kk + 1][0], s[2 * kk + 1][1], ph[2], pl[2]);
            psplit2(s[2 * kk + 1][2], s[2 * kk + 1][3], ph[3], pl[3]);
#pragma unroll
            for (int pr = 0; pr < 4; pr++) {
                uint32_t bvh[4], bvl[4];
                ldsm_x4_t(bvh, vHb + (uint32_t)(kk * 16 * AP + pr * 16) * 2);
                ldsm_x4_t(bvl, vLb + (uint32_t)(kk * 16 * AP + pr * 16) * 2);
                mma_bf16(o[2 * pr],     ph, bvh[0], bvh[1]);
                mma_bf16(o[2 * pr],     pl, bvh[0], bvh[1]);
                mma_bf16(o[2 * pr],     ph, bvl[0], bvl[1]);
                mma_bf16(o[2 * pr + 1], ph, bvh[2], bvh[3]);
                mma_bf16(o[2 * pr + 1], pl, bvh[2], bvh[3]);
                mma_bf16(o[2 * pr + 1], ph, bvl[2], bvl[3]);
            }
        }
    }

    // ---- epilogue: normalize, split, store ----
    float inv0 = 1.0f / l0, inv1 = 1.0f / l1;
    int r0 = w * 16 + (lane >> 2), cb = (lane & 3) * 2;
#pragma unroll
    for (int j = 0; j < 8; j++) {
        int col = h * 64 + 8 * j + cb;
        {
            int tok = t0 + qb * 64 + r0;
            float v0 = o[j][0] * inv0, v1 = o[j][1] * inv0;
            bf16 h0, l0b, h1, l1b;
            split(v0, h0, l0b); split(v1, h1, l1b);
            uint32_t ph = ((uint32_t)__bfloat16_as_ushort(h1) << 16) | __bfloat16_as_ushort(h0);
            uint32_t pq = ((uint32_t)__bfloat16_as_ushort(l1b) << 16) | __bfloat16_as_ushort(l0b);
            *(uint32_t*)&g_ath[(size_t)tok * DIMSZ + col] = ph;
            *(uint32_t*)&g_atl[(size_t)tok * DIMSZ + col] = pq;
        }
        {
            int tok = t0 + qb * 64 + r0 + 8;
            float v0 = o[j][2] * inv1, v1 = o[j][3] * inv1;
            bf16 h0, l0b, h1, l1b;
            split(v0, h0, l0b); split(v1, h1, l1b);
            uint32_t ph = ((uint32_t)__bfloat16_as_ushort(h1) << 16) | __bfloat16_as_ushort(h0);
            uint32_t pq = ((uint32_t)__bfloat16_as_ushort(l1b) << 16) | __bfloat16_as_ushort(l0b);
            *(uint32_t*)&g_ath[(size_t)tok * DIMSZ + col] = ph;
            *(uint32_t*)&g_atl[(size_t)tok * DIMSZ + col] = pq;
        }
    }
}

// ---------------------------------------------------------------------------
extern "C" void kernel_launch(void* const* d_in, const int* in_sizes, int n_in,
                              void* d_out, int out_size) {
    const float* x     = (const float*)d_in[0];
    const float* gamma = (const float*)d_in[1];
    const float* w_qkv = (const float*)d_in[2];
    const float* w_out = (const float*)d_in[3];
    float*       out   = (float*)d_out;
    (void)in_sizes; (void)n_in; (void)out_size;

    float* p_qkv;
    bf16 *p_xnh, *p_xnl, *p_wqh, *p_wql, *p_ath, *p_atl, *p_woh, *p_wol;
    cudaGetSymbolAddress((void**)&p_qkv, g_qkv);
    cudaGetSymbolAddress((void**)&p_xnh, g_xnh);
    cudaGetSymbolAddress((void**)&p_xnl, g_xnl);
    cudaGetSymbolAddress((void**)&p_wqh, g_wqh);
    cudaGetSymbolAddress((void**)&p_wql, g_wql);
    cudaGetSymbolAddress((void**)&p_ath, g_ath);
    cudaGetSymbolAddress((void**)&p_atl, g_atl);
    cudaGetSymbolAddress((void**)&p_woh, g_woh);
    cudaGetSymbolAddress((void**)&p_wol, g_wol);

    rmsnorm_kernel<<<TOKENS, 256>>>(x, gamma);
    tsplit_kernel<<<dim3(QKV_N / 32, DIMSZ / 32), dim3(32, 8)>>>(w_qkv, p_wqh, p_wql, DIMSZ, QKV_N);
    tsplit_kernel<<<dim3(DIMSZ / 32, DIMSZ / 32), dim3(32, 8)>>>(w_out, p_woh, p_wol, DIMSZ, DIMSZ);
    gemm_mma<<<dim3(QKV_N / 128, TOKENS / 128), 256>>>(p_xnh, p_xnl, p_wqh, p_wql, p_qkv, QKV_N);
    attn_mma<<<dim3(NSEQ / 64, 2 * HEADS), 128>>>();
    gemm_mma<<<dim3(DIMSZ / 128, TOKENS / 128), 256>>>(p_ath, p_atl, p_woh, p_wol, out, DIMSZ);
}

// round 12
// speedup vs baseline: 3.4527x; 1.1723x over previous
#include <cuda_runtime.h>
#include <cuda_bf16.h>
#include <cstdint>

#define TOKENS 4096
#define DIMSZ  1024
#define NSEQ   2048
#define HEADS  16
#define QKV_N  3072

typedef __nv_bfloat16 bf16;

// Scratch (device globals per harness rules; 16B-aligned for cp.async/uint4)
__device__ __align__(16) bf16 g_xnh [TOKENS * DIMSZ];
__device__ __align__(16) bf16 g_xnl [TOKENS * DIMSZ];
__device__ __align__(16) bf16 g_wqh [QKV_N * DIMSZ];
__device__ __align__(16) bf16 g_wql [QKV_N * DIMSZ];
__device__ __align__(16) bf16 g_qkvh[TOKENS * QKV_N];   // split QKV (Q pre-scaled)
__device__ __align__(16) bf16 g_qkvl[TOKENS * QKV_N];
__device__ __align__(16) bf16 g_ath [TOKENS * DIMSZ];
__device__ __align__(16) bf16 g_atl [TOKENS * DIMSZ];
__device__ __align__(16) bf16 g_woh [DIMSZ * DIMSZ];
__device__ __align__(16) bf16 g_wol [DIMSZ * DIMSZ];

__device__ __forceinline__ uint32_t smem_u32(const void* p) {
    uint32_t a;
    asm("{ .reg .u64 t; cvta.to.shared.u64 t, %1; cvt.u32.u64 %0, t; }" : "=r"(a) : "l"(p));
    return a;
}
__device__ __forceinline__ void split(float v, bf16& h, bf16& l) {
    h = __float2bfloat16(v);
    l = __float2bfloat16(v - __bfloat162float(h));
}
__device__ __forceinline__ void ldsm_x4(uint32_t* r, uint32_t addr) {
    asm volatile("ldmatrix.sync.aligned.m8n8.x4.shared.b16 {%0,%1,%2,%3}, [%4];"
        : "=r"(r[0]), "=r"(r[1]), "=r"(r[2]), "=r"(r[3]) : "r"(addr));
}
__device__ __forceinline__ void ldsm_x4_t(uint32_t* r, uint32_t addr) {
    asm volatile("ldmatrix.sync.aligned.m8n8.x4.trans.shared.b16 {%0,%1,%2,%3}, [%4];"
        : "=r"(r[0]), "=r"(r[1]), "=r"(r[2]), "=r"(r[3]) : "r"(addr));
}
__device__ __forceinline__ void mma_bf16(float* c, const uint32_t* a, uint32_t b0, uint32_t b1) {
    asm volatile(
        "mma.sync.aligned.m16n8k16.row.col.f32.bf16.bf16.f32 "
        "{%0,%1,%2,%3}, {%4,%5,%6,%7}, {%8,%9}, {%0,%1,%2,%3};"
        : "+f"(c[0]), "+f"(c[1]), "+f"(c[2]), "+f"(c[3])
        : "r"(a[0]), "r"(a[1]), "r"(a[2]), "r"(a[3]), "r"(b0), "r"(b1));
}
__device__ __forceinline__ void psplit2(float x, float y, uint32_t& ph, uint32_t& pl) {
    bf16 hx = __float2bfloat16(x), hy = __float2bfloat16(y);
    bf16 lx = __float2bfloat16(x - __bfloat162float(hx));
    bf16 ly = __float2bfloat16(y - __bfloat162float(hy));
    ph = ((uint32_t)__bfloat16_as_ushort(hy) << 16) | __bfloat16_as_ushort(hx);
    pl = ((uint32_t)__bfloat16_as_ushort(ly) << 16) | __bfloat16_as_ushort(lx);
}

#define CP16(dst, src)  asm volatile("cp.async.cg.shared.global [%0], [%1], 16;" :: "r"(dst), "l"(src))
#define CP_COMMIT()     asm volatile("cp.async.commit_group;" ::: "memory")
#define CP_WAIT(n)      asm volatile("cp.async.wait_group %0;" :: "n"(n) : "memory")

// ---------------------------------------------------------------------------
// RMSNorm -> split bf16 hi/lo
// ---------------------------------------------------------------------------
__global__ void __launch_bounds__(256) rmsnorm_kernel(const float* __restrict__ x,
                                                      const float* __restrict__ gamma) {
    int row = blockIdx.x;
    int tid = threadIdx.x;
    const float4 v = ((const float4*)(x + (size_t)row * DIMSZ))[tid];
    float ss = v.x * v.x + v.y * v.y + v.z * v.z + v.w * v.w;
#pragma unroll
    for (int off = 16; off >= 1; off >>= 1)
        ss += __shfl_xor_sync(0xffffffffu, ss, off);
    __shared__ float red[8];
    int lane = tid & 31, wid = tid >> 5;
    if (lane == 0) red[wid] = ss;
    __syncthreads();
    if (wid == 0) {
        float t = (lane < 8) ? red[lane] : 0.0f;
#pragma unroll
        for (int off = 4; off >= 1; off >>= 1)
            t += __shfl_xor_sync(0xffffffffu, t, off);
        if (lane == 0) red[0] = t;
    }
    __syncthreads();
    float norm = fmaxf(sqrtf(red[0]), 1e-12f);
    float scl = 32.0f / norm;
    const float4 g = ((const float4*)gamma)[tid];
    float o0 = v.x * scl * g.x, o1 = v.y * scl * g.y;
    float o2 = v.z * scl * g.z, o3 = v.w * scl * g.w;
    __align__(8) bf16 hh[4], ll[4];
    split(o0, hh[0], ll[0]); split(o1, hh[1], ll[1]);
    split(o2, hh[2], ll[2]); split(o3, hh[3], ll[3]);
    size_t off = (size_t)row * DIMSZ + tid * 4;
    *(uint2*)&g_xnh[off] = *(uint2*)hh;
    *(uint2*)&g_xnl[off] = *(uint2*)ll;
}

// ---------------------------------------------------------------------------
// Transpose + split: W[K][N] fp32 -> Th/Tl[N][K] bf16
// ---------------------------------------------------------------------------
__global__ void tsplit_kernel(const float* __restrict__ W, bf16* __restrict__ Th,
                              bf16* __restrict__ Tl, int K, int N) {
    __shared__ float s[32][33];
    int tx = threadIdx.x, ty = threadIdx.y;
    int n0 = blockIdx.x * 32, k0 = blockIdx.y * 32;
#pragma unroll
    for (int j = 0; j < 32; j += 8)
        s[ty + j][tx] = W[(size_t)(k0 + ty + j) * N + n0 + tx];
    __syncthreads();
#pragma unroll
    for (int j = 0; j < 32; j += 8) {
        float v = s[tx][ty + j];
        bf16 h, l; split(v, h, l);
        size_t o = (size_t)(n0 + ty + j) * K + k0 + tx;
        Th[o] = h; Tl[o] = l;
    }
}

// ---------------------------------------------------------------------------
// Split-bf16 mma.sync GEMM with cp.async 2-stage pipeline.
// C[M,N] = A[M,1024] @ Bt[N,1024]^T ~= Ah·Bh + Ah·Bl + Al·Bh
// SPLIT=1: write split bf16 (Ch/Cl), scaling cols < 1024 by 0.125 (Q).
// SPLIT=0: write fp32 C.
// ---------------------------------------------------------------------------
#define SPITCH 40
#define G_AB  (128 * SPITCH * 2)   // 10240 B per array
#define G_STG (4 * G_AB)           // 40960 B per stage
#define GEMM_SMEM (2 * G_STG)      // 81920 B

template<int SPLIT>
__global__ void __launch_bounds__(256, 2) gemm_mma(
        const bf16* __restrict__ Ah, const bf16* __restrict__ Al,
        const bf16* __restrict__ Bh, const bf16* __restrict__ Bl,
        float* __restrict__ C, bf16* __restrict__ Ch, bf16* __restrict__ Cl, int N) {
    extern __shared__ char smraw[];
    uint32_t sbase = smem_u32(smraw);
    int tid = threadIdx.x, lane = tid & 31, wid = tid >> 5;
    int wm = wid >> 2, wn = wid & 3;
    int bm = blockIdx.y * 128, bn = blockIdx.x * 128;

    const bf16* g0 = Ah + (size_t)bm * DIMSZ;
    const bf16* g1 = Al + (size_t)bm * DIMSZ;
    const bf16* g2 = Bh + (size_t)bn * DIMSZ;
    const bf16* g3 = Bl + (size_t)bn * DIMSZ;

    int rowA = wm * 64 + (lane & 7) + ((lane >> 3) & 1) * 8;
    int koffA = (lane >> 4) * 8;
    uint32_t aoff = (uint32_t)(rowA * SPITCH + koffA) * 2;
    int nrow = wn * 32 + (lane & 7) + ((lane >> 4) & 1) * 8;
    int koffB = ((lane >> 3) & 1) * 8;
    uint32_t boff = (uint32_t)(nrow * SPITCH + koffB) * 2;

    float c[4][4][4];
#pragma unroll
    for (int i = 0; i < 4; i++)
#pragma unroll
        for (int j = 0; j < 4; j++)
#pragma unroll
            for (int k = 0; k < 4; k++) c[i][j][k] = 0.0f;

    // per-thread copy coords (2 chunks/array): row, chunk
    int cprow0 = tid >> 2,             cpch0 = (tid & 3) * 8;
    int cprow1 = (tid + 256) >> 2,     cpch1 = (tid & 3) * 8;
    uint32_t cpd0 = (uint32_t)(cprow0 * SPITCH + cpch0) * 2;
    uint32_t cpd1 = (uint32_t)(cprow1 * SPITCH + cpch1) * 2;

#define G_ISSUE(s, stg) do {                                                      \
    int k0_ = (s) * 32;                                                           \
    uint32_t db_ = sbase + (stg) * G_STG;                                         \
    CP16(db_ + 0 * G_AB + cpd0, g0 + (size_t)cprow0 * DIMSZ + k0_ + cpch0);       \
    CP16(db_ + 1 * G_AB + cpd0, g1 + (size_t)cprow0 * DIMSZ + k0_ + cpch0);       \
    CP16(db_ + 2 * G_AB + cpd0, g2 + (size_t)cprow0 * DIMSZ + k0_ + cpch0);       \
    CP16(db_ + 3 * G_AB + cpd0, g3 + (size_t)cprow0 * DIMSZ + k0_ + cpch0);       \
    CP16(db_ + 0 * G_AB + cpd1, g0 + (size_t)cprow1 * DIMSZ + k0_ + cpch1);       \
    CP16(db_ + 1 * G_AB + cpd1, g1 + (size_t)cprow1 * DIMSZ + k0_ + cpch1);       \
    CP16(db_ + 2 * G_AB + cpd1, g2 + (size_t)cprow1 * DIMSZ + k0_ + cpch1);       \
    CP16(db_ + 3 * G_AB + cpd1, g3 + (size_t)cprow1 * DIMSZ + k0_ + cpch1);       \
    CP_COMMIT();                                                                  \
} while (0)

    G_ISSUE(0, 0);

    const int NSLAB = DIMSZ / 32;  // 32
    for (int s = 0; s < NSLAB; s++) {
        int stg = s & 1;
        if (s < NSLAB - 1) { G_ISSUE(s + 1, stg ^ 1); CP_WAIT(1); }
        else               { CP_WAIT(0); }
        __syncthreads();
        uint32_t sb = sbase + stg * G_STG;
        uint32_t aHb = sb + aoff, aLb = sb + G_AB + aoff;
        uint32_t bHb = sb + 2 * G_AB + boff, bLb = sb + 3 * G_AB + boff;
#pragma unroll
        for (int kk = 0; kk < 2; kk++) {
            uint32_t ko = kk * 32;
            uint32_t aH[4][4], aL[4][4], bH[2][4], bL[2][4];
#pragma unroll
            for (int mt = 0; mt < 4; mt++) {
                ldsm_x4(aH[mt], aHb + mt * (16 * SPITCH * 2) + ko);
                ldsm_x4(aL[mt], aLb + mt * (16 * SPITCH * 2) + ko);
            }
#pragma unroll
            for (int pr = 0; pr < 2; pr++) {
                ldsm_x4(bH[pr], bHb + pr * (16 * SPITCH * 2) + ko);
                ldsm_x4(bL[pr], bLb + pr * (16 * SPITCH * 2) + ko);
            }
#pragma unroll
            for (int mt = 0; mt < 4; mt++)
#pragma unroll
                for (int nt = 0; nt < 4; nt++) {
                    int pr = nt >> 1, hf = (nt & 1) * 2;
                    mma_bf16(c[mt][nt], aH[mt], bH[pr][hf], bH[pr][hf + 1]);
                    mma_bf16(c[mt][nt], aH[mt], bL[pr][hf], bL[pr][hf + 1]);
                    mma_bf16(c[mt][nt], aL[mt], bH[pr][hf], bH[pr][hf + 1]);
                }
        }
        __syncthreads();
    }

    float sc = (SPLIT && bn < 1024) ? 0.125f : 1.0f;
#pragma unroll
    for (int mt = 0; mt < 4; mt++)
#pragma unroll
        for (int nt = 0; nt < 4; nt++) {
            int r0 = bm + wm * 64 + mt * 16 + (lane >> 2);
            int col = bn + wn * 32 + nt * 8 + (lane & 3) * 2;
            if (SPLIT) {
#pragma unroll
                for (int hrow = 0; hrow < 2; hrow++) {
                    float v0 = c[mt][nt][2 * hrow] * sc, v1 = c[mt][nt][2 * hrow + 1] * sc;
                    uint32_t ph, pl;
                    psplit2(v0, v1, ph, pl);
                    size_t o = (size_t)(r0 + 8 * hrow) * N + col;
                    *(uint32_t*)&Ch[o] = ph;
                    *(uint32_t*)&Cl[o] = pl;
                }
            } else {
                *(float2*)&C[(size_t)r0 * N + col]       = make_float2(c[mt][nt][0], c[mt][nt][1]);
                *(float2*)&C[(size_t)(r0 + 8) * N + col] = make_float2(c[mt][nt][2], c[mt][nt][3]);
            }
        }
#undef G_ISSUE
}

// ---------------------------------------------------------------------------
// Causal flash attention, split-bf16 mma.sync, cp.async double-buffered K/V.
// K/V already split in g_qkvh/g_qkvl (Q pre-scaled by 0.125 in GEMM epilogue).
// ---------------------------------------------------------------------------
#define AP    72
#define A_AB  (64 * AP * 2)        // 9216 B per array
#define A_STG (4 * A_AB)           // 36864 B per stage
#define ATTN_SMEM (2 * A_STG)      // 73728 B

__global__ void __launch_bounds__(128) attn_mma() {
    extern __shared__ char smraw[];
    uint32_t sbase = smem_u32(smraw);
    int tid = threadIdx.x, lane = tid & 31, w = tid >> 5;
    int qb = blockIdx.x, bh = blockIdx.y;
    int b = bh >> 4, h = bh & 15;
    int t0 = b * NSEQ;

    // per-thread copy coords (4 iters x 4 arrays)
#define A_ISSUE(kb, stg) do {                                                        \
    uint32_t db_ = sbase + (stg) * A_STG;                                            \
    _Pragma("unroll")                                                                \
    for (int t = 0; t < 4; t++) {                                                    \
        int idx = tid + t * 128;                                                     \
        int row = idx >> 3, ch = (idx & 7) * 8;                                      \
        uint32_t doff = (uint32_t)(row * AP + ch) * 2;                               \
        size_t g = (size_t)(t0 + (kb) * 64 + row) * QKV_N + h * 64 + ch;             \
        CP16(db_ + 0 * A_AB + doff, &g_qkvh[g + 1024]);                              \
        CP16(db_ + 1 * A_AB + doff, &g_qkvl[g + 1024]);                              \
        CP16(db_ + 2 * A_AB + doff, &g_qkvh[g + 2048]);                              \
        CP16(db_ + 3 * A_AB + doff, &g_qkvl[g + 2048]);                              \
    }                                                                                \
    CP_COMMIT();                                                                     \
} while (0)

    A_ISSUE(0, 0);   // K/V block 0 -> stage 0 (async, overlaps Q staging)

    // stage Q (bf16, pre-scaled) into stage-1 Kh/Kl regions
#pragma unroll
    for (int t = 0; t < 4; t++) {
        int idx = tid + t * 128;
        int row = idx >> 3, ch = (idx & 7) * 8;
        size_t g = (size_t)(t0 + qb * 64 + row) * QKV_N + h * 64 + ch;
        uint32_t doff = (uint32_t)(row * AP + ch) * 2;
        *(uint4*)(smraw + A_STG + 0 * A_AB + doff) = *(const uint4*)&g_qkvh[g];
        *(uint4*)(smraw + A_STG + 1 * A_AB + doff) = *(const uint4*)&g_qkvl[g];
    }
    __syncthreads();
    uint32_t qh[4][4], ql[4][4];
    {
        int rowA = w * 16 + (lane & 7) + ((lane >> 3) & 1) * 8;
        int koffA = (lane >> 4) * 8;
        uint32_t aHb = sbase + A_STG + 0 * A_AB + (uint32_t)(rowA * AP + koffA) * 2;
        uint32_t aLb = sbase + A_STG + 1 * A_AB + (uint32_t)(rowA * AP + koffA) * 2;
#pragma unroll
        for (int k = 0; k < 4; k++) {
            ldsm_x4(qh[k], aHb + k * 32);
            ldsm_x4(ql[k], aLb + k * 32);
        }
    }
    __syncthreads();   // all warps have Q frags before stage-1 gets overwritten

    float o[8][4];
#pragma unroll
    for (int j = 0; j < 8; j++)
#pragma unroll
        for (int v = 0; v < 4; v++) o[j][v] = 0.0f;
    float m0 = -1e30f, m1 = -1e30f, l0 = 0.0f, l1 = 0.0f;

    int nrowB = (lane & 7) + ((lane >> 4) & 1) * 8;
    int koffB = ((lane >> 3) & 1) * 8;
    uint32_t kboff = (uint32_t)(nrowB * AP + koffB) * 2;
    uint32_t vboff = (uint32_t)((lane & 15) * AP + ((lane >> 4) & 1) * 8) * 2;

    for (int kb = 0; kb <= qb; kb++) {
        int stg = kb & 1;
        if (kb < qb) { A_ISSUE(kb + 1, stg ^ 1); CP_WAIT(1); }
        else         { CP_WAIT(0); }
        __syncthreads();
        uint32_t sb = sbase + stg * A_STG;
        uint32_t kHb = sb + kboff, kLb = sb + A_AB + kboff;
        uint32_t vHb = sb + 2 * A_AB + vboff, vLb = sb + 3 * A_AB + vboff;

        // ---- S = Q K^T ----
        float s[8][4];
#pragma unroll
        for (int j = 0; j < 8; j++)
#pragma unroll
            for (int v = 0; v < 4; v++) s[j][v] = 0.0f;
#pragma unroll
        for (int k = 0; k < 4; k++)
#pragma unroll
            for (int pr = 0; pr < 4; pr++) {
                uint32_t bh_[4], bl_[4];
                ldsm_x4(bh_, kHb + pr * (16 * AP * 2) + k * 32);
                ldsm_x4(bl_, kLb + pr * (16 * AP * 2) + k * 32);
                mma_bf16(s[2 * pr],     qh[k], bh_[0], bh_[1]);
                mma_bf16(s[2 * pr],     qh[k], bl_[0], bl_[1]);
                mma_bf16(s[2 * pr],     ql[k], bh_[0], bh_[1]);
                mma_bf16(s[2 * pr + 1], qh[k], bh_[2], bh_[3]);
                mma_bf16(s[2 * pr + 1], qh[k], bl_[2], bl_[3]);
                mma_bf16(s[2 * pr + 1], ql[k], bh_[2], bh_[3]);
            }

        int r0 = w * 16 + (lane >> 2);
        int cb = (lane & 3) * 2;
        if (kb == qb) {
#pragma unroll
            for (int j = 0; j < 8; j++) {
                int c0 = 8 * j + cb;
                if (c0     > r0    ) s[j][0] = -1e30f;
                if (c0 + 1 > r0    ) s[j][1] = -1e30f;
                if (c0     > r0 + 8) s[j][2] = -1e30f;
                if (c0 + 1 > r0 + 8) s[j][3] = -1e30f;
            }
        }

        // ---- online softmax (2 rows/thread) ----
        float tm0 = -1e30f, tm1 = -1e30f;
#pragma unroll
        for (int j = 0; j < 8; j++) {
            tm0 = fmaxf(tm0, fmaxf(s[j][0], s[j][1]));
            tm1 = fmaxf(tm1, fmaxf(s[j][2], s[j][3]));
        }
        tm0 = fmaxf(tm0, __shfl_xor_sync(0xffffffffu, tm0, 1));
        tm0 = fmaxf(tm0, __shfl_xor_sync(0xffffffffu, tm0, 2));
        tm1 = fmaxf(tm1, __shfl_xor_sync(0xffffffffu, tm1, 1));
        tm1 = fmaxf(tm1, __shfl_xor_sync(0xffffffffu, tm1, 2));
        float mn0 = fmaxf(m0, tm0), mn1 = fmaxf(m1, tm1);
        float al0 = __expf(m0 - mn0), al1 = __expf(m1 - mn1);
        m0 = mn0; m1 = mn1;
        float sum0 = 0.0f, sum1 = 0.0f;
#pragma unroll
        for (int j = 0; j < 8; j++) {
            s[j][0] = __expf(s[j][0] - mn0); sum0 += s[j][0];
            s[j][1] = __expf(s[j][1] - mn0); sum0 += s[j][1];
            s[j][2] = __expf(s[j][2] - mn1); sum1 += s[j][2];
            s[j][3] = __expf(s[j][3] - mn1); sum1 += s[j][3];
        }
        sum0 += __shfl_xor_sync(0xffffffffu, sum0, 1);
        sum0 += __shfl_xor_sync(0xffffffffu, sum0, 2);
        sum1 += __shfl_xor_sync(0xffffffffu, sum1, 1);
        sum1 += __shfl_xor_sync(0xffffffffu, sum1, 2);
        l0 = l0 * al0 + sum0;
        l1 = l1 * al1 + sum1;
#pragma unroll
        for (int j = 0; j < 8; j++) {
            o[j][0] *= al0; o[j][1] *= al0;
            o[j][2] *= al1; o[j][3] *= al1;
        }

        // ---- O += P V ----
#pragma unroll
        for (int kk = 0; kk < 4; kk++) {
            uint32_t ph[4], pl[4];
            psplit2(s[2 * kk][0],     s[2 * kk][1],     ph[0], pl[0]);
            psplit2(s[2 * kk][2],     s[2 * kk][3],     ph[1], pl[1]);
            psplit2(s[2 * kk + 1][0], s[2 * kk + 1][1], ph[2], pl[2]);
            psplit2(s[2 * kk + 1][2], s[2 * kk + 1][3], ph[3], pl[3]);
#pragma unroll
            for (int pr = 0; pr < 4; pr++) {
                uint32_t bvh[4], bvl[4];
                ldsm_x4_t(bvh, vHb + (uint32_t)(kk * 16 * AP + pr * 16) * 2);
                ldsm_x4_t(bvl, vLb + (uint32_t)(kk * 16 * AP + pr * 16) * 2);
                mma_bf16(o[2 * pr],     ph, bvh[0], bvh[1]);
                mma_bf16(o[2 * pr],     pl, bvh[0], bvh[1]);
                mma_bf16(o[2 * pr],     ph, bvl[0], bvl[1]);
                mma_bf16(o[2 * pr + 1], ph, bvh[2], bvh[3]);
                mma_bf16(o[2 * pr + 1], pl, bvh[2], bvh[3]);
                mma_bf16(o[2 * pr + 1], ph, bvl[2], bvl[3]);
            }
        }
        __syncthreads();   // all warps done with this stage before it is refilled
    }

    // ---- epilogue ----
    float inv0 = 1.0f / l0, inv1 = 1.0f / l1;
    int r0 = w * 16 + (lane >> 2), cb = (lane & 3) * 2;
#pragma unroll
    for (int j = 0; j < 8; j++) {
        int col = h * 64 + 8 * j + cb;
        {
            int tok = t0 + qb * 64 + r0;
            uint32_t ph, pl;
            psplit2(o[j][0] * inv0, o[j][1] * inv0, ph, pl);
            *(uint32_t*)&g_ath[(size_t)tok * DIMSZ + col] = ph;
            *(uint32_t*)&g_atl[(size_t)tok * DIMSZ + col] = pl;
        }
        {
            int tok = t0 + qb * 64 + r0 + 8;
            uint32_t ph, pl;
            psplit2(o[j][2] * inv1, o[j][3] * inv1, ph, pl);
            *(uint32_t*)&g_ath[(size_t)tok * DIMSZ + col] = ph;
            *(uint32_t*)&g_atl[(size_t)tok * DIMSZ + col] = pl;
        }
    }
#undef A_ISSUE
}

// ---------------------------------------------------------------------------
extern "C" void kernel_launch(void* const* d_in, const int* in_sizes, int n_in,
                              void* d_out, int out_size) {
    const float* x     = (const float*)d_in[0];
    const float* gamma = (const float*)d_in[1];
    const float* w_qkv = (const float*)d_in[2];
    const float* w_out = (const float*)d_in[3];
    float*       out   = (float*)d_out;
    (void)in_sizes; (void)n_in; (void)out_size;

    bf16 *p_xnh, *p_xnl, *p_wqh, *p_wql, *p_qvh, *p_qvl, *p_ath, *p_atl, *p_woh, *p_wol;
    cudaGetSymbolAddress((void**)&p_xnh, g_xnh);
    cudaGetSymbolAddress((void**)&p_xnl, g_xnl);
    cudaGetSymbolAddress((void**)&p_wqh, g_wqh);
    cudaGetSymbolAddress((void**)&p_wql, g_wql);
    cudaGetSymbolAddress((void**)&p_qvh, g_qkvh);
    cudaGetSymbolAddress((void**)&p_qvl, g_qkvl);
    cudaGetSymbolAddress((void**)&p_ath, g_ath);
    cudaGetSymbolAddress((void**)&p_atl, g_atl);
    cudaGetSymbolAddress((void**)&p_woh, g_woh);
    cudaGetSymbolAddress((void**)&p_wol, g_wol);

    static int attr_set = 0;
    if (!attr_set) {
        cudaFuncSetAttribute(gemm_mma<1>, cudaFuncAttributeMaxDynamicSharedMemorySize, GEMM_SMEM);
        cudaFuncSetAttribute(gemm_mma<0>, cudaFuncAttributeMaxDynamicSharedMemorySize, GEMM_SMEM);
        cudaFuncSetAttribute(attn_mma,    cudaFuncAttributeMaxDynamicSharedMemorySize, ATTN_SMEM);
        attr_set = 1;
    }

    rmsnorm_kernel<<<TOKENS, 256>>>(x, gamma);
    tsplit_kernel<<<dim3(QKV_N / 32, DIMSZ / 32), dim3(32, 8)>>>(w_qkv, p_wqh, p_wql, DIMSZ, QKV_N);
    tsplit_kernel<<<dim3(DIMSZ / 32, DIMSZ / 32), dim3(32, 8)>>>(w_out, p_woh, p_wol, DIMSZ, DIMSZ);
    gemm_mma<1><<<dim3(QKV_N / 128, TOKENS / 128), 256, GEMM_SMEM>>>(
        p_xnh, p_xnl, p_wqh, p_wql, nullptr, p_qvh, p_qvl, QKV_N);
    attn_mma<<<dim3(NSEQ / 64, 2 * HEADS), 128, ATTN_SMEM>>>();
    gemm_mma<0><<<dim3(DIMSZ / 128, TOKENS / 128), 256, GEMM_SMEM>>>(
        p_ath, p_atl, p_woh, p_wol, out, nullptr, nullptr, DIMSZ);
}